// round 8
// baseline (speedup 1.0000x reference)
#include <cuda_runtime.h>
#include <cuda_fp16.h>

#define USER_NUM 100000
#define ITEM_NUM 50000
#define NTOT     (USER_NUM + ITEM_NUM)     // 150000
#define EMB      64
#define NNZ      3000000
#define EPS      0.1f
#define NELEM    (NTOT * EMB)              // 9,600,000
#define CAP      64                        // bucket capacity per row (max cnt ~42)

// ---- static scratch (referenced ONLY in device code; zero-init at load) ----
__device__ __half g_halfA[NELEM];          // fp16 ego0 (gather source, layer 0)
__device__ __half g_halfB[NELEM];          // fp16 e1
__device__ __half g_halfC[NELEM];          // fp16 e2
__device__ int    g_cnt[NTOT];             // zero at entry (layer2 self-cleans)
__device__ float2 g_pair[(long long)NTOT * CAP];  // {val, col} buckets, 512B/row

// ---- fp16 helpers ----------------------------------------------------------
__device__ __forceinline__ float4 ldh4(const __half* p) {
    uint2 u = *(const uint2*)p;
    __half2 h0 = *reinterpret_cast<__half2*>(&u.x);
    __half2 h1 = *reinterpret_cast<__half2*>(&u.y);
    float2 f0 = __half22float2(h0);
    float2 f1 = __half22float2(h1);
    return make_float4(f0.x, f0.y, f1.x, f1.y);
}
__device__ __forceinline__ void sth4(__half* p, float4 v) {
    __half2 h0 = __floats2half2_rn(v.x, v.y);
    __half2 h1 = __floats2half2_rn(v.z, v.w);
    uint2 u;
    u.x = *reinterpret_cast<unsigned*>(&h0);
    u.y = *reinterpret_cast<unsigned*>(&h1);
    *(uint2*)p = u;
}

// ---------------------------------------------------------------------------
// single build kernel: halfA = fp16(concat(user,item));
//   pos = cnt[rows[i]]++ (atomic);  pair[rows[i]*CAP + pos] = {val, col}
// (g_cnt is zero on entry: load-time zero-init, then layer2 re-zeroes it)
// ---------------------------------------------------------------------------
__global__ void build_kernel(const float* __restrict__ ue,
                             const float* __restrict__ ie,
                             const float* __restrict__ vals,
                             const int*   __restrict__ rows,
                             const int*   __restrict__ cols) {
    int idx = blockIdx.x * blockDim.x + threadIdx.x;
    if (idx < NELEM / 4) {
        float4 v;
        if (idx < USER_NUM * EMB / 4) v = ((const float4*)ue)[idx];
        else                          v = ((const float4*)ie)[idx - USER_NUM * EMB / 4];
        sth4(g_halfA + (long long)idx * 4, v);
    }
    if (idx < NNZ) {
        int r   = rows[idx];
        int pos = atomicAdd(&g_cnt[r], 1);
        g_pair[(long long)r * CAP + pos] = make_float2(vals[idx], __int_as_float(cols[idx]));
    }
}

// ---------------------------------------------------------------------------
// Fused layer: gather-SpMM (buckets, half-warp per row, fp16 8B gather,
//              fp32 accum) + sign-noise perturb; layer2 averages -> out.
// ---------------------------------------------------------------------------
__device__ __forceinline__ float sgn(float x) {
    return (x > 0.f) ? 1.f : ((x < 0.f) ? -1.f : 0.f);
}

// L = 0: halfA -> halfB.  L = 1: halfB -> halfC.  L = 2: halfC -> averaged out.
template <int L>
__global__ void __launch_bounds__(256) layer_kernel(const float* __restrict__ noise_k,
                                                    const float* __restrict__ ue,
                                                    const float* __restrict__ ie,
                                                    float* __restrict__ out) {
    const __half* __restrict__ egoIn = (L == 0) ? g_halfA : ((L == 1) ? g_halfB : g_halfC);

    int hw = (blockIdx.x * blockDim.x + threadIdx.x) >> 4;  // half-warp = row
    int l  = threadIdx.x & 15;                              // 4-elem slice
    if (hw >= NTOT) return;

    int cnt = g_cnt[hw];
    const float2* __restrict__ pr = g_pair + (long long)hw * CAP;

    float4 a = make_float4(0.f, 0.f, 0.f, 0.f);

    int j = 0;
    for (; j + 4 <= cnt; j += 4) {                          // unroll-4 for MLP
        float2 p0 = pr[j],     p1 = pr[j + 1];
        float2 p2 = pr[j + 2], p3 = pr[j + 3];
        float4 x0 = ldh4(egoIn + (long long)__float_as_int(p0.y) * EMB + 4 * l);
        float4 x1 = ldh4(egoIn + (long long)__float_as_int(p1.y) * EMB + 4 * l);
        float4 x2 = ldh4(egoIn + (long long)__float_as_int(p2.y) * EMB + 4 * l);
        float4 x3 = ldh4(egoIn + (long long)__float_as_int(p3.y) * EMB + 4 * l);
        a.x += p0.x * x0.x; a.y += p0.x * x0.y; a.z += p0.x * x0.z; a.w += p0.x * x0.w;
        a.x += p1.x * x1.x; a.y += p1.x * x1.y; a.z += p1.x * x1.z; a.w += p1.x * x1.w;
        a.x += p2.x * x2.x; a.y += p2.x * x2.y; a.z += p2.x * x2.z; a.w += p2.x * x2.w;
        a.x += p3.x * x3.x; a.y += p3.x * x3.y; a.z += p3.x * x3.z; a.w += p3.x * x3.w;
    }
    for (; j < cnt; ++j) {
        float2 p = pr[j];
        float4 x = ldh4(egoIn + (long long)__float_as_int(p.y) * EMB + 4 * l);
        a.x += p.x * x.x; a.y += p.x * x.y; a.z += p.x * x.z; a.w += p.x * x.w;
    }

    // noise row-norm over 64 elems (16 lanes x 4), shfl reduce within half-warp
    float4 n = ((const float4*)noise_k)[hw * 16 + l];
    float ss = n.x * n.x + n.y * n.y + n.z * n.z + n.w * n.w;
    ss += __shfl_xor_sync(0xffffffffu, ss, 8, 16);
    ss += __shfl_xor_sync(0xffffffffu, ss, 4, 16);
    ss += __shfl_xor_sync(0xffffffffu, ss, 2, 16);
    ss += __shfl_xor_sync(0xffffffffu, ss, 1, 16);
    float inv = EPS / fmaxf(sqrtf(ss), 1e-12f);

    float4 e;
    e.x = a.x + sgn(a.x) * n.x * inv;
    e.y = a.y + sgn(a.y) * n.y * inv;
    e.z = a.z + sgn(a.z) * n.z * inv;
    e.w = a.w + sgn(a.w) * n.w * inv;

    long long o = (long long)hw * EMB + 4 * l;              // element offset
    if (L == 0) {
        sth4(g_halfB + o, e);
    } else if (L == 1) {
        sth4(g_halfC + o, e);
    } else {
        // ego0 from the exact fp32 inputs; e1,e2 from the fp16 copies
        float4 z0;
        if (hw < USER_NUM) z0 = *(const float4*)(ue + o);
        else               z0 = *(const float4*)(ie + o - (long long)USER_NUM * EMB);
        float4 z1 = ldh4(g_halfB + o);
        float4 z2 = ldh4(g_halfC + o);
        *(float4*)(out + o) = make_float4((z0.x + z1.x + z2.x + e.x) * 0.25f,
                                          (z0.y + z1.y + z2.y + e.y) * 0.25f,
                                          (z0.z + z1.z + z2.z + e.z) * 0.25f,
                                          (z0.w + z1.w + z2.w + e.w) * 0.25f);
        if (l == 0) g_cnt[hw] = 0;                          // self-clean for next replay
    }
}

// ---------------------------------------------------------------------------
// launch: 4 kernels total
// Inputs: 0 user_emb, 1 item_emb, 2 adj_vals, 3 noise, 4 adj_rows, 5 adj_cols
// ---------------------------------------------------------------------------
extern "C" void kernel_launch(void* const* d_in, const int* in_sizes, int n_in,
                              void* d_out, int out_size) {
    const float* ue    = (const float*)d_in[0];
    const float* ie    = (const float*)d_in[1];
    const float* vals  = (const float*)d_in[2];
    const float* noise = (const float*)d_in[3];
    const int*   rows  = (const int*)d_in[4];
    const int*   cols  = (const int*)d_in[5];
    float* out = (float*)d_out;
    (void)in_sizes; (void)n_in; (void)out_size;

    const int bld_blocks = (NNZ + 255) / 256;               // covers NELEM/4 too
    const int lay_blocks = (NTOT * 16 + 255) / 256;         // half-warp per row

    build_kernel<<<bld_blocks, 256>>>(ue, ie, vals, rows, cols);

    layer_kernel<0><<<lay_blocks, 256>>>(noise + 0LL * NELEM, ue, ie, out);
    layer_kernel<1><<<lay_blocks, 256>>>(noise + 1LL * NELEM, ue, ie, out);
    layer_kernel<2><<<lay_blocks, 256>>>(noise + 2LL * NELEM, ue, ie, out);
}

// round 9
// speedup vs baseline: 1.1304x; 1.1304x over previous
#include <cuda_runtime.h>
#include <cuda_fp16.h>

#define USER_NUM 100000
#define ITEM_NUM 50000
#define NTOT     (USER_NUM + ITEM_NUM)     // 150000
#define EMB      64
#define NNZ      3000000
#define EPS      0.1f
#define NELEM    (NTOT * EMB)              // 9,600,000
#define NBLK     ((NTOT + 1023) / 1024)    // 147 scan blocks
#define SBATCH   4
#define SSTRIDE  ((NNZ + SBATCH - 1) / SBATCH)   // 750000

// ---- static scratch (referenced ONLY in device code; zero-init at load) ----
__device__ __half g_halfA[NELEM];          // fp16 ego0 (gather source, layer 0)
__device__ __half g_halfB[NELEM];          // fp16 e1
__device__ __half g_halfC[NELEM];          // fp16 e2
__device__ int    g_cnt[NTOT];             // zero at entry (scan1 self-cleans)
__device__ int    g_row_ptr[NTOT + 1];
__device__ int    g_cursor[NTOT];
__device__ int    g_blocksum[NBLK];
__device__ float2 g_pair[NNZ];             // dense {val, col} grouped by row

// ---- fp16 helpers ----------------------------------------------------------
__device__ __forceinline__ float4 ldh4(const __half* p) {
    uint2 u = *(const uint2*)p;
    __half2 h0 = *reinterpret_cast<__half2*>(&u.x);
    __half2 h1 = *reinterpret_cast<__half2*>(&u.y);
    float2 f0 = __half22float2(h0);
    float2 f1 = __half22float2(h1);
    return make_float4(f0.x, f0.y, f1.x, f1.y);
}
__device__ __forceinline__ void sth4(__half* p, float4 v) {
    __half2 h0 = __floats2half2_rn(v.x, v.y);
    __half2 h1 = __floats2half2_rn(v.z, v.w);
    uint2 u;
    u.x = *reinterpret_cast<unsigned*>(&h0);
    u.y = *reinterpret_cast<unsigned*>(&h1);
    *(uint2*)p = u;
}

// ---------------------------------------------------------------------------
// fused init + histogram: halfA = fp16(concat(user,item)); cnt[rows[i]]++
// ---------------------------------------------------------------------------
__global__ void init_hist_kernel(const float* __restrict__ ue,
                                 const float* __restrict__ ie,
                                 const int*   __restrict__ rows) {
    int idx = blockIdx.x * blockDim.x + threadIdx.x;
    if (idx == 0) g_row_ptr[NTOT] = NNZ;
    if (idx < NELEM / 4) {
        float4 v;
        if (idx < USER_NUM * EMB / 4) v = ((const float4*)ue)[idx];
        else                          v = ((const float4*)ie)[idx - USER_NUM * EMB / 4];
        sth4(g_halfA + (long long)idx * 4, v);
    }
    if (idx < NNZ) atomicAdd(&g_cnt[rows[idx]], 1);
}

// ---------------------------------------------------------------------------
// CSR build: per-block scan (self-cleaning cnt) -> blockoff apply -> scatter
// ---------------------------------------------------------------------------
__global__ void scan1_kernel() {                 // per-1024-block exclusive scan
    __shared__ int sh[1024];
    int i = blockIdx.x * 1024 + threadIdx.x;
    int v = (i < NTOT) ? g_cnt[i] : 0;
    if (i < NTOT) g_cnt[i] = 0;                  // self-clean for next replay
    sh[threadIdx.x] = v;
    __syncthreads();
    #pragma unroll
    for (int o = 1; o < 1024; o <<= 1) {
        int t = (threadIdx.x >= o) ? sh[threadIdx.x - o] : 0;
        __syncthreads();
        sh[threadIdx.x] += t;
        __syncthreads();
    }
    if (i < NTOT) g_row_ptr[i] = sh[threadIdx.x] - v;      // exclusive within block
    if (threadIdx.x == 1023) g_blocksum[blockIdx.x] = sh[1023];
}

__global__ void scan23_kernel() {                // blockoff reduce + apply + cursors
    __shared__ int sh[256];
    int i    = blockIdx.x * 256 + threadIdx.x;
    int sblk = (blockIdx.x * 256) >> 10;
    int t    = threadIdx.x;
    sh[t] = (t < NBLK && t < sblk) ? g_blocksum[t] : 0;
    __syncthreads();
    #pragma unroll
    for (int o = 128; o; o >>= 1) {
        if (t < o) sh[t] += sh[t + o];
        __syncthreads();
    }
    int off = sh[0];
    if (i >= NTOT) return;
    int v = g_row_ptr[i] + off;
    g_row_ptr[i] = v;
    g_cursor[i]  = v;
}

// batched scatter: 4 independent load->atomic->store chains per thread (MLP x4)
__global__ void __launch_bounds__(256) scatter_kernel(const float* __restrict__ vals,
                                                      const int* __restrict__ rows,
                                                      const int* __restrict__ cols) {
    int t = blockIdx.x * blockDim.x + threadIdx.x;
    if (t >= SSTRIDE) return;
    int i0 = t, i1 = t + SSTRIDE, i2 = t + 2 * SSTRIDE, i3 = t + 3 * SSTRIDE;
    bool b1 = i1 < NNZ, b2 = i2 < NNZ, b3 = i3 < NNZ;

    int    r0 = rows[i0],               r1 = b1 ? rows[i1] : 0;
    int    r2 = b2 ? rows[i2] : 0,      r3 = b3 ? rows[i3] : 0;
    float  v0 = vals[i0],               v1 = b1 ? vals[i1] : 0.f;
    float  v2 = b2 ? vals[i2] : 0.f,    v3 = b3 ? vals[i3] : 0.f;
    int    c0 = cols[i0],               c1 = b1 ? cols[i1] : 0;
    int    c2 = b2 ? cols[i2] : 0,      c3 = b3 ? cols[i3] : 0;

    int p0 = atomicAdd(&g_cursor[r0], 1);
    int p1 = b1 ? atomicAdd(&g_cursor[r1], 1) : 0;
    int p2 = b2 ? atomicAdd(&g_cursor[r2], 1) : 0;
    int p3 = b3 ? atomicAdd(&g_cursor[r3], 1) : 0;

    g_pair[p0] = make_float2(v0, __int_as_float(c0));
    if (b1) g_pair[p1] = make_float2(v1, __int_as_float(c1));
    if (b2) g_pair[p2] = make_float2(v2, __int_as_float(c2));
    if (b3) g_pair[p3] = make_float2(v3, __int_as_float(c3));
}

// ---------------------------------------------------------------------------
// Fused layer: gather-SpMM (CSR, half-warp per row, fp16 8B gather, fp32 accum)
//              + sign-noise perturb; last layer averages ego0+e1+e2+e3 -> out.
// ---------------------------------------------------------------------------
__device__ __forceinline__ float sgn(float x) {
    return (x > 0.f) ? 1.f : ((x < 0.f) ? -1.f : 0.f);
}

// L = 0: halfA -> halfB.  L = 1: halfB -> halfC.  L = 2: halfC -> averaged out.
template <int L>
__global__ void __launch_bounds__(256) layer_kernel(const float* __restrict__ noise_k,
                                                    const float* __restrict__ ue,
                                                    const float* __restrict__ ie,
                                                    float* __restrict__ out) {
    const __half* __restrict__ egoIn = (L == 0) ? g_halfA : ((L == 1) ? g_halfB : g_halfC);

    int hw = (blockIdx.x * blockDim.x + threadIdx.x) >> 4;  // half-warp = row
    int l  = threadIdx.x & 15;                              // 4-elem slice
    if (hw >= NTOT) return;

    int beg = g_row_ptr[hw];
    int end = g_row_ptr[hw + 1];

    float4 a = make_float4(0.f, 0.f, 0.f, 0.f);

    int j = beg;
    for (; j + 4 <= end; j += 4) {                          // unroll-4 for MLP
        float2 p0 = g_pair[j],     p1 = g_pair[j + 1];
        float2 p2 = g_pair[j + 2], p3 = g_pair[j + 3];
        float4 x0 = ldh4(egoIn + (long long)__float_as_int(p0.y) * EMB + 4 * l);
        float4 x1 = ldh4(egoIn + (long long)__float_as_int(p1.y) * EMB + 4 * l);
        float4 x2 = ldh4(egoIn + (long long)__float_as_int(p2.y) * EMB + 4 * l);
        float4 x3 = ldh4(egoIn + (long long)__float_as_int(p3.y) * EMB + 4 * l);
        a.x += p0.x * x0.x; a.y += p0.x * x0.y; a.z += p0.x * x0.z; a.w += p0.x * x0.w;
        a.x += p1.x * x1.x; a.y += p1.x * x1.y; a.z += p1.x * x1.z; a.w += p1.x * x1.w;
        a.x += p2.x * x2.x; a.y += p2.x * x2.y; a.z += p2.x * x2.z; a.w += p2.x * x2.w;
        a.x += p3.x * x3.x; a.y += p3.x * x3.y; a.z += p3.x * x3.z; a.w += p3.x * x3.w;
    }
    for (; j < end; ++j) {
        float2 p = g_pair[j];
        float4 x = ldh4(egoIn + (long long)__float_as_int(p.y) * EMB + 4 * l);
        a.x += p.x * x.x; a.y += p.x * x.y; a.z += p.x * x.z; a.w += p.x * x.w;
    }

    // noise row-norm over 64 elems (16 lanes x 4), shfl reduce within half-warp
    float4 n = ((const float4*)noise_k)[hw * 16 + l];
    float ss = n.x * n.x + n.y * n.y + n.z * n.z + n.w * n.w;
    ss += __shfl_xor_sync(0xffffffffu, ss, 8, 16);
    ss += __shfl_xor_sync(0xffffffffu, ss, 4, 16);
    ss += __shfl_xor_sync(0xffffffffu, ss, 2, 16);
    ss += __shfl_xor_sync(0xffffffffu, ss, 1, 16);
    float inv = EPS / fmaxf(sqrtf(ss), 1e-12f);

    float4 e;
    e.x = a.x + sgn(a.x) * n.x * inv;
    e.y = a.y + sgn(a.y) * n.y * inv;
    e.z = a.z + sgn(a.z) * n.z * inv;
    e.w = a.w + sgn(a.w) * n.w * inv;

    long long o = (long long)hw * EMB + 4 * l;              // element offset
    if (L == 0) {
        sth4(g_halfB + o, e);
    } else if (L == 1) {
        sth4(g_halfC + o, e);
    } else {
        // ego0 from the exact fp32 inputs; e1,e2 from the fp16 copies
        float4 z0;
        if (hw < USER_NUM) z0 = *(const float4*)(ue + o);
        else               z0 = *(const float4*)(ie + o - (long long)USER_NUM * EMB);
        float4 z1 = ldh4(g_halfB + o);
        float4 z2 = ldh4(g_halfC + o);
        *(float4*)(out + o) = make_float4((z0.x + z1.x + z2.x + e.x) * 0.25f,
                                          (z0.y + z1.y + z2.y + e.y) * 0.25f,
                                          (z0.z + z1.z + z2.z + e.z) * 0.25f,
                                          (z0.w + z1.w + z2.w + e.w) * 0.25f);
    }
}

// ---------------------------------------------------------------------------
// launch
// Inputs: 0 user_emb, 1 item_emb, 2 adj_vals, 3 noise, 4 adj_rows, 5 adj_cols
// ---------------------------------------------------------------------------
extern "C" void kernel_launch(void* const* d_in, const int* in_sizes, int n_in,
                              void* d_out, int out_size) {
    const float* ue    = (const float*)d_in[0];
    const float* ie    = (const float*)d_in[1];
    const float* vals  = (const float*)d_in[2];
    const float* noise = (const float*)d_in[3];
    const int*   rows  = (const int*)d_in[4];
    const int*   cols  = (const int*)d_in[5];
    float* out = (float*)d_out;
    (void)in_sizes; (void)n_in; (void)out_size;

    const int nnz_blocks  = (NNZ + 255) / 256;              // covers NELEM/4 too
    const int row_blocks  = (NTOT + 255) / 256;
    const int sct_blocks  = (SSTRIDE + 255) / 256;
    const int lay_blocks  = (NTOT * 16 + 255) / 256;        // half-warp per row

    init_hist_kernel<<<nnz_blocks, 256>>>(ue, ie, rows);

    scan1_kernel<<<NBLK, 1024>>>();
    scan23_kernel<<<row_blocks, 256>>>();
    scatter_kernel<<<sct_blocks, 256>>>(vals, rows, cols);

    // 3 fused layers: halfA -> halfB -> halfC -> averaged out
    layer_kernel<0><<<lay_blocks, 256>>>(noise + 0LL * NELEM, ue, ie, out);
    layer_kernel<1><<<lay_blocks, 256>>>(noise + 1LL * NELEM, ue, ie, out);
    layer_kernel<2><<<lay_blocks, 256>>>(noise + 2LL * NELEM, ue, ie, out);
}